// round 1
// baseline (speedup 1.0000x reference)
#include <cuda_runtime.h>
#include <cstdint>

#define B_ 2
#define T_ 16
#define N_ 2000
#define F_ 16
#define E_ 32000
#define H_ 4
#define C_ 32
#define D_ 64
#define FF_ 2048
#define G_ (B_*T_)      /* 32  */
#define ET_ (E_+N_)     /* 34000 */
#define BN_ (B_*N_)     /* 4000 */
#define GN_ (G_*N_)     /* 64000 */

// ---------------- scratch (static device globals; no allocation) -------------
__device__ float g_h[GN_ * 128];          // h: [G,N,H*C]
__device__ float g_asrc[GN_ * 4];         // per-head src logit term
__device__ float g_adst[GN_ * 4];
__device__ float g_prep[8];               // c_edge[0..3], ew_mean at [4]
__device__ int   g_deg[2048];
__device__ int   g_off[N_ + 1];
__device__ int   g_cur[N_];
__device__ int   g_csr[ET_];
__device__ float g_y[BN_ * T_ * D_];      // [b*N+n][t][d]
__device__ float g_z[BN_ * D_];           // post-LN1, last timestep
__device__ float g_ff[(size_t)BN_ * FF_]; // relu(z@W1+b1)

// ---------------- prep: edge-weight mean + per-head edge constants -----------
__global__ void k_prep(const float* __restrict__ ew,
                       const float* __restrict__ W_edge,
                       const float* __restrict__ att_edge) {
    __shared__ float sred[256];
    int tid = threadIdx.x;
    float s = 0.f;
    for (int i = tid; i < E_; i += 256) s += ew[i];
    sred[tid] = s;
    __syncthreads();
    for (int o = 128; o > 0; o >>= 1) {
        if (tid < o) sred[tid] += sred[tid + o];
        __syncthreads();
    }
    if (tid == 0) g_prep[4] = sred[0] / (float)E_;
    if (tid < 4) {
        float c = 0.f;
        for (int j = 0; j < 32; j++) c += W_edge[tid * 32 + j] * att_edge[tid * 32 + j];
        g_prep[tid] = c;
    }
}

// ---------------- CSR build --------------------------------------------------
__global__ void k_zero_deg() {
    int i = blockIdx.x * blockDim.x + threadIdx.x;
    if (i < 2048) g_deg[i] = 0;
}

__global__ void k_count(const int* __restrict__ ei) {
    int e = blockIdx.x * blockDim.x + threadIdx.x;
    if (e >= ET_) return;
    int d = (e < E_) ? ei[E_ + e] : (e - E_);
    atomicAdd(&g_deg[d], 1);
}

__global__ void k_scan() {
    __shared__ int buf[2][2048];
    int t = threadIdx.x;
    for (int i = t; i < 2048; i += 1024) buf[0][i] = (i < N_) ? g_deg[i] : 0;
    __syncthreads();
    int cur = 0;
    for (int off = 1; off < 2048; off <<= 1) {
        int nxt = cur ^ 1;
        for (int i = t; i < 2048; i += 1024) {
            int v = buf[cur][i];
            if (i >= off) v += buf[cur][i - off];
            buf[nxt][i] = v;
        }
        __syncthreads();
        cur = nxt;
    }
    for (int i = t; i < N_; i += 1024) {
        int excl = (i == 0) ? 0 : buf[cur][i - 1];
        g_off[i] = excl;
        g_cur[i] = excl;
    }
    if (t == 0) g_off[N_] = buf[cur][N_ - 1];
}

__global__ void k_scatter(const int* __restrict__ ei) {
    int e = blockIdx.x * blockDim.x + threadIdx.x;
    if (e >= ET_) return;
    int d = (e < E_) ? ei[E_ + e] : (e - E_);
    int pos = atomicAdd(&g_cur[d], 1);
    g_csr[pos] = e;
}

// ---------------- h = x @ W_gat; per-head attn scalar terms ------------------
// one warp per (g,n) row: 16->128 GEMV, then dot with att_src/att_dst
__global__ void __launch_bounds__(256) k_h(const float* __restrict__ x,
                                           const float* __restrict__ Wg,
                                           const float* __restrict__ as_w,
                                           const float* __restrict__ ad_w) {
    __shared__ float Wgs[16 * 128];
    __shared__ float s_as[128], s_ad[128];
    int tid = threadIdx.x;
    for (int i = tid; i < 2048; i += 256) Wgs[i] = Wg[i];
    for (int i = tid; i < 128; i += 256) { s_as[i] = as_w[i]; s_ad[i] = ad_w[i]; }
    __syncthreads();
    int w = blockIdx.x * 8 + (tid >> 5);
    if (w >= GN_) return;
    int lane = tid & 31;
    const float* xr = x + (size_t)w * 16;
    float xf = (lane < 16) ? xr[lane] : 0.f;
    float4 h4 = make_float4(0.f, 0.f, 0.f, 0.f);
    const float4* Wg4 = (const float4*)Wgs;
#pragma unroll
    for (int f = 0; f < 16; f++) {
        float xv = __shfl_sync(0xffffffffu, xf, f);
        float4 wv = Wg4[f * 32 + lane];
        h4.x += xv * wv.x; h4.y += xv * wv.y; h4.z += xv * wv.z; h4.w += xv * wv.w;
    }
    ((float4*)g_h)[(size_t)w * 32 + lane] = h4;
    float4 a = ((const float4*)s_as)[lane];
    float4 d = ((const float4*)s_ad)[lane];
    float vs = h4.x * a.x + h4.y * a.y + h4.z * a.z + h4.w * a.w;
    float vd = h4.x * d.x + h4.y * d.y + h4.z * d.z + h4.w * d.w;
#pragma unroll
    for (int off = 1; off < 8; off <<= 1) {
        vs += __shfl_xor_sync(0xffffffffu, vs, off);
        vd += __shfl_xor_sync(0xffffffffu, vd, off);
    }
    if ((lane & 7) == 0) {
        g_asrc[w * 4 + (lane >> 3)] = vs;
        g_adst[w * 4 + (lane >> 3)] = vd;
    }
}

// ---------------- GAT aggregate + head-mean + bias + proj to D=64 ------------
// one warp per (g, dst). Lane owns 4 contiguous channels (one head / 8 lanes).
__global__ void __launch_bounds__(256) k_agg(const int* __restrict__ ei,
                                             const float* __restrict__ ew,
                                             const float* __restrict__ gbias,
                                             const float* __restrict__ Wp,
                                             const float* __restrict__ bp) {
    __shared__ float Wps[32 * 64];
    __shared__ float bias_s[32];
    __shared__ float bp_s[64];
    __shared__ float ce_s[4];
    __shared__ float ewm_s;
    int tid = threadIdx.x;
    for (int i = tid; i < 2048; i += 256) Wps[i] = Wp[i];
    if (tid < 32) bias_s[tid] = gbias[tid];
    if (tid < 64) bp_s[tid] = bp[tid];
    if (tid < 4)  ce_s[tid] = g_prep[tid];
    if (tid == 8) ewm_s = g_prep[4];
    __syncthreads();
    int w = blockIdx.x * 8 + (tid >> 5);
    if (w >= GN_) return;
    int lane = tid & 31;
    int g = w / N_;
    int dst = w - g * N_;
    int hd = lane >> 3;
    float ad = g_adst[((size_t)g * N_ + dst) * 4 + hd];
    float ce = ce_s[hd];
    float acc0 = 0.f, acc1 = 0.f, acc2 = 0.f, acc3 = 0.f, den = 0.f;
    int beg = g_off[dst], end = g_off[dst + 1];
    const float*  hbase = g_h + (size_t)g * N_ * 128;
    const float*  abase = g_asrc + (size_t)g * N_ * 4;
    for (int i = beg; i < end; i++) {
        int e = g_csr[i];
        int s;
        float wgt;
        if (e < E_) { s = ei[e]; wgt = ew[e]; }
        else        { s = e - E_; wgt = ewm_s; }
        float as = abase[s * 4 + hd];
        float lg = as + ad + ce * wgt;
        lg = (lg > 0.f) ? lg : 0.2f * lg;
        float p = __expf(lg);
        den += p;
        float4 hv = *((const float4*)(hbase + (size_t)s * 128) + lane);
        acc0 += p * hv.x; acc1 += p * hv.y; acc2 += p * hv.z; acc3 += p * hv.w;
    }
    float inv = 1.f / (den + 1e-16f);
    acc0 *= inv; acc1 *= inv; acc2 *= inv; acc3 *= inv;
    // mean over heads: sum lanes l, l^8, l^16, l^24
    acc0 += __shfl_xor_sync(0xffffffffu, acc0, 8);  acc0 += __shfl_xor_sync(0xffffffffu, acc0, 16);
    acc1 += __shfl_xor_sync(0xffffffffu, acc1, 8);  acc1 += __shfl_xor_sync(0xffffffffu, acc1, 16);
    acc2 += __shfl_xor_sync(0xffffffffu, acc2, 8);  acc2 += __shfl_xor_sync(0xffffffffu, acc2, 16);
    acc3 += __shfl_xor_sync(0xffffffffu, acc3, 8);  acc3 += __shfl_xor_sync(0xffffffffu, acc3, 16);
    int cb = (lane & 7) * 4;
    float og0 = acc0 * 0.25f + bias_s[cb + 0];
    float og1 = acc1 * 0.25f + bias_s[cb + 1];
    float og2 = acc2 * 0.25f + bias_s[cb + 2];
    float og3 = acc3 * 0.25f + bias_s[cb + 3];
    // project 32 -> 64: lane computes outputs d0, d0+1
    int d0 = lane * 2;
    float y0 = bp_s[d0], y1 = bp_s[d0 + 1];
#pragma unroll
    for (int sl = 0; sl < 8; sl++) {
        float v0 = __shfl_sync(0xffffffffu, og0, sl);
        float v1 = __shfl_sync(0xffffffffu, og1, sl);
        float v2 = __shfl_sync(0xffffffffu, og2, sl);
        float v3 = __shfl_sync(0xffffffffu, og3, sl);
        int c = sl * 4;
        float2 w0 = *(const float2*)&Wps[(c + 0) * 64 + d0];
        float2 w1 = *(const float2*)&Wps[(c + 1) * 64 + d0];
        float2 w2 = *(const float2*)&Wps[(c + 2) * 64 + d0];
        float2 w3 = *(const float2*)&Wps[(c + 3) * 64 + d0];
        y0 += v0 * w0.x + v1 * w1.x + v2 * w2.x + v3 * w3.x;
        y1 += v0 * w0.y + v1 * w1.y + v2 * w2.y + v3 * w3.y;
    }
    int b = g >> 4;          // T = 16
    int t = g & 15;
    float2* out = (float2*)&g_y[(((size_t)(b * N_ + dst)) * T_ + t) * D_];
    out[lane] = make_float2(y0, y1);
}

// ---------------- transformer: qkv (q only at t=15), attn, +res, LN1 ---------
__global__ void __launch_bounds__(128) k_attn(const float* __restrict__ Wqkv,
                                              const float* __restrict__ bqkv,
                                              const float* __restrict__ Wo,
                                              const float* __restrict__ bo,
                                              const float* __restrict__ ln1g,
                                              const float* __restrict__ ln1b) {
    __shared__ float ys[16 * 64];
    __shared__ float ks[16 * 64];
    __shared__ float vs[16 * 64];
    __shared__ float qv[64];
    __shared__ float ctx[64];
    __shared__ float red[4];
    int row = blockIdx.x;
    int tid = threadIdx.x;
    const float* yrow = g_y + (size_t)row * (T_ * D_);
    for (int i = tid; i < 1024; i += 128) ys[i] = yrow[i];
    __syncthreads();
    // K and V for all 16 timesteps
    for (int i = tid; i < 2048; i += 128) {
        int which = i >> 10;         // 0=k, 1=v
        int rem = i & 1023;
        int t = rem >> 6;
        int d = rem & 63;
        int col = 64 + which * 64 + d;
        float a = bqkv[col];
        const float* yt = &ys[t * 64];
#pragma unroll
        for (int j = 0; j < 64; j++) a += yt[j] * Wqkv[j * 192 + col];
        if (which) vs[t * 64 + d] = a; else ks[t * 64 + d] = a;
    }
    // Q at last timestep only
    if (tid < 64) {
        float a = bqkv[tid];
        const float* yt = &ys[15 * 64];
#pragma unroll
        for (int j = 0; j < 64; j++) a += yt[j] * Wqkv[j * 192 + tid];
        qv[tid] = a;
    }
    __syncthreads();
    int wid = tid >> 5, lane = tid & 31;
    if (lane < 16) {
        float s = 0.f;
        const float* kr = &ks[lane * 64 + wid * 16];
        const float* qr = &qv[wid * 16];
#pragma unroll
        for (int j = 0; j < 16; j++) s += qr[j] * kr[j];
        s *= 0.25f;
        float m = s;
#pragma unroll
        for (int off = 1; off < 16; off <<= 1) m = fmaxf(m, __shfl_xor_sync(0x0000ffffu, m, off));
        float p = __expf(s - m);
        float dn = p;
#pragma unroll
        for (int off = 1; off < 16; off <<= 1) dn += __shfl_xor_sync(0x0000ffffu, dn, off);
        p /= dn;
        float o = 0.f;
#pragma unroll
        for (int t2 = 0; t2 < 16; t2++) {
            float pv = __shfl_sync(0x0000ffffu, p, t2);
            o += pv * vs[t2 * 64 + wid * 16 + lane];
        }
        ctx[wid * 16 + lane] = o;
    }
    __syncthreads();
    float r = 0.f;
    if (tid < 64) {
        float o = bo[tid];
#pragma unroll
        for (int j = 0; j < 64; j++) o += ctx[j] * Wo[j * 64 + tid];
        r = ys[15 * 64 + tid] + o;
        float s1 = r, s2 = r * r;
#pragma unroll
        for (int off = 1; off < 32; off <<= 1) {
            s1 += __shfl_xor_sync(0xffffffffu, s1, off);
            s2 += __shfl_xor_sync(0xffffffffu, s2, off);
        }
        if (lane == 0) { red[wid * 2] = s1; red[wid * 2 + 1] = s2; }
    }
    __syncthreads();
    if (tid < 64) {
        float s1 = red[0] + red[2];
        float s2 = red[1] + red[3];
        float mu = s1 * (1.f / 64.f);
        float var = s2 * (1.f / 64.f) - mu * mu;
        float z = (r - mu) * rsqrtf(var + 1e-5f) * ln1g[tid] + ln1b[tid];
        g_z[(size_t)row * 64 + tid] = z;
    }
}

// ---------------- FFN layer 1: relu(Z @ W1 + b1) -----------------------------
// tile 64 rows x 64 cols, 256 threads, 4x4 register tile
__global__ void __launch_bounds__(256) k_ffn1(const float* __restrict__ W1,
                                              const float* __restrict__ b1) {
    __shared__ float ZsT[64 * 65];   // transposed, padded
    __shared__ float W1s[64 * 64];
    int tid = threadIdx.x;
    int rb = blockIdx.x * 64;
    int cb = blockIdx.y * 64;
    for (int i = tid; i < 4096; i += 256) {
        int rr = i >> 6, k = i & 63;
        int gr = rb + rr;
        ZsT[k * 65 + rr] = (gr < BN_) ? g_z[(size_t)gr * 64 + k] : 0.f;
    }
    for (int i = tid; i < 4096; i += 256) {
        int k = i >> 6, c = i & 63;
        W1s[i] = W1[(size_t)k * FF_ + cb + c];
    }
    __syncthreads();
    int tx = tid & 15, ty = tid >> 4;
    float acc[4][4];
#pragma unroll
    for (int i = 0; i < 4; i++)
#pragma unroll
        for (int j = 0; j < 4; j++) acc[i][j] = 0.f;
#pragma unroll 16
    for (int kk = 0; kk < 64; kk++) {
        float a0 = ZsT[kk * 65 + 4 * ty + 0];
        float a1 = ZsT[kk * 65 + 4 * ty + 1];
        float a2 = ZsT[kk * 65 + 4 * ty + 2];
        float a3 = ZsT[kk * 65 + 4 * ty + 3];
        float4 bv = *(const float4*)&W1s[kk * 64 + 4 * tx];
        acc[0][0] += a0 * bv.x; acc[0][1] += a0 * bv.y; acc[0][2] += a0 * bv.z; acc[0][3] += a0 * bv.w;
        acc[1][0] += a1 * bv.x; acc[1][1] += a1 * bv.y; acc[1][2] += a1 * bv.z; acc[1][3] += a1 * bv.w;
        acc[2][0] += a2 * bv.x; acc[2][1] += a2 * bv.y; acc[2][2] += a2 * bv.z; acc[2][3] += a2 * bv.w;
        acc[3][0] += a3 * bv.x; acc[3][1] += a3 * bv.y; acc[3][2] += a3 * bv.z; acc[3][3] += a3 * bv.w;
    }
    int col = cb + 4 * tx;
    float4 bb = *(const float4*)&b1[col];
#pragma unroll
    for (int i = 0; i < 4; i++) {
        int gr = rb + 4 * ty + i;
        if (gr < BN_) {
            float4 o;
            o.x = fmaxf(acc[i][0] + bb.x, 0.f);
            o.y = fmaxf(acc[i][1] + bb.y, 0.f);
            o.z = fmaxf(acc[i][2] + bb.z, 0.f);
            o.w = fmaxf(acc[i][3] + bb.w, 0.f);
            *(float4*)&g_ff[(size_t)gr * FF_ + col] = o;
        }
    }
}

// ---------------- FFN layer 2 + residual + LN2 -> output ---------------------
// tile 32 rows x 64 cols, 256 threads, 2x4 register tile, k-chunks of 64
__global__ void __launch_bounds__(256) k_ffn2(const float* __restrict__ W2,
                                              const float* __restrict__ b2,
                                              const float* __restrict__ ln2g,
                                              const float* __restrict__ ln2b,
                                              float* __restrict__ out) {
    __shared__ float FsT[64 * 33];
    __shared__ float W2s[64 * 64];
    int tid = threadIdx.x;
    int rb = blockIdx.x * 32;
    int tx = tid & 15, ty = tid >> 4;
    float acc[2][4];
#pragma unroll
    for (int i = 0; i < 2; i++)
#pragma unroll
        for (int j = 0; j < 4; j++) acc[i][j] = 0.f;
    for (int kc = 0; kc < FF_; kc += 64) {
        for (int i = tid; i < 2048; i += 256) {
            int rr = i >> 6, k = i & 63;
            FsT[k * 33 + rr] = g_ff[(size_t)(rb + rr) * FF_ + kc + k];
        }
        for (int i = tid; i < 4096; i += 256) {
            int k = i >> 6, d = i & 63;
            W2s[i] = W2[(size_t)(kc + k) * 64 + d];
        }
        __syncthreads();
#pragma unroll 16
        for (int kk = 0; kk < 64; kk++) {
            float a0 = FsT[kk * 33 + 2 * ty + 0];
            float a1 = FsT[kk * 33 + 2 * ty + 1];
            float4 bv = *(const float4*)&W2s[kk * 64 + 4 * tx];
            acc[0][0] += a0 * bv.x; acc[0][1] += a0 * bv.y; acc[0][2] += a0 * bv.z; acc[0][3] += a0 * bv.w;
            acc[1][0] += a1 * bv.x; acc[1][1] += a1 * bv.y; acc[1][2] += a1 * bv.z; acc[1][3] += a1 * bv.w;
        }
        __syncthreads();
    }
    int col = 4 * tx;
    float4 bb = *(const float4*)&b2[col];
    float4 gg = *(const float4*)&ln2g[col];
    float4 be = *(const float4*)&ln2b[col];
#pragma unroll
    for (int i = 0; i < 2; i++) {
        int gr = rb + 2 * ty + i;
        const float* zr = &g_z[(size_t)gr * 64];
        float v0 = acc[i][0] + bb.x + zr[col + 0];
        float v1 = acc[i][1] + bb.y + zr[col + 1];
        float v2 = acc[i][2] + bb.z + zr[col + 2];
        float v3 = acc[i][3] + bb.w + zr[col + 3];
        float s1 = v0 + v1 + v2 + v3;
        float s2 = v0 * v0 + v1 * v1 + v2 * v2 + v3 * v3;
#pragma unroll
        for (int off = 1; off < 16; off <<= 1) {
            s1 += __shfl_xor_sync(0xffffffffu, s1, off);
            s2 += __shfl_xor_sync(0xffffffffu, s2, off);
        }
        float mu = s1 * (1.f / 64.f);
        float var = s2 * (1.f / 64.f) - mu * mu;
        float inv = rsqrtf(var + 1e-5f);
        float4 o;
        o.x = (v0 - mu) * inv * gg.x + be.x;
        o.y = (v1 - mu) * inv * gg.y + be.y;
        o.z = (v2 - mu) * inv * gg.z + be.z;
        o.w = (v3 - mu) * inv * gg.w + be.w;
        *(float4*)&out[(size_t)gr * 64 + col] = o;
    }
}

// ---------------- launch ----------------------------------------------------
extern "C" void kernel_launch(void* const* d_in, const int* in_sizes, int n_in,
                              void* d_out, int out_size) {
    const float* x_seq    = (const float*)d_in[0];
    const int*   eidx     = (const int*)d_in[1];
    const float* eweight  = (const float*)d_in[2];
    const float* W_gat    = (const float*)d_in[3];
    const float* att_src  = (const float*)d_in[4];
    const float* att_dst  = (const float*)d_in[5];
    const float* W_edge   = (const float*)d_in[6];
    const float* att_edge = (const float*)d_in[7];
    const float* gat_bias = (const float*)d_in[8];
    const float* W_proj   = (const float*)d_in[9];
    const float* b_proj   = (const float*)d_in[10];
    const float* Wqkv     = (const float*)d_in[11];
    const float* bqkv     = (const float*)d_in[12];
    const float* Wo       = (const float*)d_in[13];
    const float* bo       = (const float*)d_in[14];
    const float* ln1_g    = (const float*)d_in[15];
    const float* ln1_b    = (const float*)d_in[16];
    const float* W1       = (const float*)d_in[17];
    const float* b1       = (const float*)d_in[18];
    const float* W2       = (const float*)d_in[19];
    const float* b2       = (const float*)d_in[20];
    const float* ln2_g    = (const float*)d_in[21];
    const float* ln2_b    = (const float*)d_in[22];
    float* out = (float*)d_out;

    k_prep<<<1, 256>>>(eweight, W_edge, att_edge);
    k_zero_deg<<<2, 1024>>>();
    k_count<<<(ET_ + 255) / 256, 256>>>(eidx);
    k_scan<<<1, 1024>>>();
    k_scatter<<<(ET_ + 255) / 256, 256>>>(eidx);
    k_h<<<GN_ / 8, 256>>>(x_seq, W_gat, att_src, att_dst);
    k_agg<<<GN_ / 8, 256>>>(eidx, eweight, gat_bias, W_proj, b_proj);
    k_attn<<<BN_, 128>>>(Wqkv, bqkv, Wo, bo, ln1_g, ln1_b);
    {
        dim3 grid((BN_ + 63) / 64, FF_ / 64);
        k_ffn1<<<grid, 256>>>(W1, b1);
    }
    k_ffn2<<<BN_ / 32, 256>>>(W2, b2, ln2_g, ln2_b, out);
}

// round 2
// speedup vs baseline: 1.2346x; 1.2346x over previous
#include <cuda_runtime.h>
#include <cstdint>

#define B_ 2
#define T_ 16
#define N_ 2000
#define F_ 16
#define E_ 32000
#define H_ 4
#define C_ 32
#define D_ 64
#define FF_ 2048
#define G_ (B_*T_)      /* 32  */
#define ET_ (E_+N_)     /* 34000 */
#define BN_ (B_*N_)     /* 4000 */
#define GN_ (G_*N_)     /* 64000 */

// ---------------- scratch (static device globals; no allocation) -------------
__device__ float g_h[GN_ * 128];          // h: [G,N,H*C]
__device__ float g_asrc[GN_ * 4];
__device__ float g_adst[GN_ * 4];
__device__ float g_prep[8];               // c_edge[0..3], ew_mean at [4]
__device__ int   g_deg[2048];
__device__ int   g_off[N_ + 1];
__device__ int   g_cur[N_];
__device__ int   g_csr[ET_];
__device__ float g_y[GN_ * D_];           // [bn][t][d]  (row rn = bn*16+t)
__device__ float g_kv[(size_t)GN_ * 128]; // [rn][0:64)=K, [64:128)=V
__device__ float g_q[BN_ * D_];           // Q at t=15
__device__ float g_z[BN_ * D_];           // post-LN1
__device__ float g_ff[(size_t)BN_ * FF_]; // relu(z@W1+b1)
__device__ float g_acc[4][BN_ * D_];      // ffn2 split-K partials

// ---------------- prep: zero deg + edge-weight mean + per-head edge consts ---
__global__ void k_prep(const float* __restrict__ ew,
                       const float* __restrict__ W_edge,
                       const float* __restrict__ att_edge) {
    __shared__ float sred[256];
    int tid = threadIdx.x;
    for (int i = tid; i < 2048; i += 256) g_deg[i] = 0;
    float s = 0.f;
    for (int i = tid; i < E_; i += 256) s += ew[i];
    sred[tid] = s;
    __syncthreads();
    for (int o = 128; o > 0; o >>= 1) {
        if (tid < o) sred[tid] += sred[tid + o];
        __syncthreads();
    }
    if (tid == 0) g_prep[4] = sred[0] / (float)E_;
    if (tid < 4) {
        float c = 0.f;
        for (int j = 0; j < 32; j++) c += W_edge[tid * 32 + j] * att_edge[tid * 32 + j];
        g_prep[tid] = c;
    }
}

// ---------------- CSR build --------------------------------------------------
__global__ void k_count(const int* __restrict__ ei) {
    int e = blockIdx.x * blockDim.x + threadIdx.x;
    if (e >= ET_) return;
    int d = (e < E_) ? ei[E_ + e] : (e - E_);
    atomicAdd(&g_deg[d], 1);
}

__global__ void k_scan() {
    __shared__ int ws[32];
    int t = threadIdx.x;                 // 1024 threads, 2 elems each
    int i0 = 2 * t, i1 = 2 * t + 1;
    int a = (i0 < N_) ? g_deg[i0] : 0;
    int b = (i1 < N_) ? g_deg[i1] : 0;
    int v = a + b;
    int lane = t & 31, wid = t >> 5;
#pragma unroll
    for (int off = 1; off < 32; off <<= 1) {
        int n = __shfl_up_sync(0xffffffffu, v, off);
        if (lane >= off) v += n;
    }
    if (lane == 31) ws[wid] = v;
    __syncthreads();
    if (t < 32) {
        int u = ws[t];
#pragma unroll
        for (int off = 1; off < 32; off <<= 1) {
            int n = __shfl_up_sync(0xffffffffu, u, off);
            if (t >= off) u += n;
        }
        ws[t] = u;
    }
    __syncthreads();
    int base = (wid > 0) ? ws[wid - 1] : 0;
    int incl = v + base;
    int ex0 = incl - a - b;
    if (i0 <= N_) { g_off[i0] = ex0; if (i0 < N_) g_cur[i0] = ex0; }
    if (i1 <= N_) { g_off[i1] = ex0 + a; if (i1 < N_) g_cur[i1] = ex0 + a; }
}

__global__ void k_scatter(const int* __restrict__ ei) {
    int e = blockIdx.x * blockDim.x + threadIdx.x;
    if (e >= ET_) return;
    int d = (e < E_) ? ei[E_ + e] : (e - E_);
    int pos = atomicAdd(&g_cur[d], 1);
    g_csr[pos] = e;
}

// ---------------- h = x @ W_gat; per-head attn scalar terms ------------------
__global__ void __launch_bounds__(256) k_h(const float* __restrict__ x,
                                           const float* __restrict__ Wg,
                                           const float* __restrict__ as_w,
                                           const float* __restrict__ ad_w) {
    __shared__ float Wgs[16 * 128];
    __shared__ float s_as[128], s_ad[128];
    int tid = threadIdx.x;
    for (int i = tid; i < 2048; i += 256) Wgs[i] = Wg[i];
    for (int i = tid; i < 128; i += 256) { s_as[i] = as_w[i]; s_ad[i] = ad_w[i]; }
    __syncthreads();
    int w = blockIdx.x * 8 + (tid >> 5);
    if (w >= GN_) return;
    int lane = tid & 31;
    const float* xr = x + (size_t)w * 16;
    float xf = (lane < 16) ? xr[lane] : 0.f;
    float4 h4 = make_float4(0.f, 0.f, 0.f, 0.f);
    const float4* Wg4 = (const float4*)Wgs;
#pragma unroll
    for (int f = 0; f < 16; f++) {
        float xv = __shfl_sync(0xffffffffu, xf, f);
        float4 wv = Wg4[f * 32 + lane];
        h4.x += xv * wv.x; h4.y += xv * wv.y; h4.z += xv * wv.z; h4.w += xv * wv.w;
    }
    ((float4*)g_h)[(size_t)w * 32 + lane] = h4;
    float4 a = ((const float4*)s_as)[lane];
    float4 d = ((const float4*)s_ad)[lane];
    float vs = h4.x * a.x + h4.y * a.y + h4.z * a.z + h4.w * a.w;
    float vd = h4.x * d.x + h4.y * d.y + h4.z * d.z + h4.w * d.w;
#pragma unroll
    for (int off = 1; off < 8; off <<= 1) {
        vs += __shfl_xor_sync(0xffffffffu, vs, off);
        vd += __shfl_xor_sync(0xffffffffu, vd, off);
    }
    if ((lane & 7) == 0) {
        g_asrc[w * 4 + (lane >> 3)] = vs;
        g_adst[w * 4 + (lane >> 3)] = vd;
    }
}

// ---------------- GAT aggregate + head-mean + bias + proj to D=64 ------------
__global__ void __launch_bounds__(256) k_agg(const int* __restrict__ ei,
                                             const float* __restrict__ ew,
                                             const float* __restrict__ gbias,
                                             const float* __restrict__ Wp,
                                             const float* __restrict__ bp) {
    __shared__ float Wps[32 * 64];
    __shared__ float bias_s[32];
    __shared__ float bp_s[64];
    __shared__ float ce_s[4];
    __shared__ float ewm_s;
    int tid = threadIdx.x;
    for (int i = tid; i < 2048; i += 256) Wps[i] = Wp[i];
    if (tid < 32) bias_s[tid] = gbias[tid];
    if (tid < 64) bp_s[tid] = bp[tid];
    if (tid < 4)  ce_s[tid] = g_prep[tid];
    if (tid == 8) ewm_s = g_prep[4];
    __syncthreads();
    int w = blockIdx.x * 8 + (tid >> 5);
    if (w >= GN_) return;
    int lane = tid & 31;
    int g = w / N_;
    int dst = w - g * N_;
    int hd = lane >> 3;
    float ad = g_adst[((size_t)g * N_ + dst) * 4 + hd];
    float ce = ce_s[hd];
    float acc0 = 0.f, acc1 = 0.f, acc2 = 0.f, acc3 = 0.f, den = 0.f;
    int beg = g_off[dst], end = g_off[dst + 1];
    const float*  hbase = g_h + (size_t)g * N_ * 128;
    const float*  abase = g_asrc + (size_t)g * N_ * 4;
    for (int i = beg; i < end; i++) {
        int e = g_csr[i];
        int s;
        float wgt;
        if (e < E_) { s = ei[e]; wgt = ew[e]; }
        else        { s = e - E_; wgt = ewm_s; }
        float as = abase[s * 4 + hd];
        float lg = as + ad + ce * wgt;
        lg = (lg > 0.f) ? lg : 0.2f * lg;
        float p = __expf(lg);
        den += p;
        float4 hv = *((const float4*)(hbase + (size_t)s * 128) + lane);
        acc0 += p * hv.x; acc1 += p * hv.y; acc2 += p * hv.z; acc3 += p * hv.w;
    }
    float inv = 1.f / (den + 1e-16f);
    acc0 *= inv; acc1 *= inv; acc2 *= inv; acc3 *= inv;
    acc0 += __shfl_xor_sync(0xffffffffu, acc0, 8);  acc0 += __shfl_xor_sync(0xffffffffu, acc0, 16);
    acc1 += __shfl_xor_sync(0xffffffffu, acc1, 8);  acc1 += __shfl_xor_sync(0xffffffffu, acc1, 16);
    acc2 += __shfl_xor_sync(0xffffffffu, acc2, 8);  acc2 += __shfl_xor_sync(0xffffffffu, acc2, 16);
    acc3 += __shfl_xor_sync(0xffffffffu, acc3, 8);  acc3 += __shfl_xor_sync(0xffffffffu, acc3, 16);
    int cb = (lane & 7) * 4;
    float og0 = acc0 * 0.25f + bias_s[cb + 0];
    float og1 = acc1 * 0.25f + bias_s[cb + 1];
    float og2 = acc2 * 0.25f + bias_s[cb + 2];
    float og3 = acc3 * 0.25f + bias_s[cb + 3];
    int d0 = lane * 2;
    float y0 = bp_s[d0], y1 = bp_s[d0 + 1];
#pragma unroll
    for (int sl = 0; sl < 8; sl++) {
        float v0 = __shfl_sync(0xffffffffu, og0, sl);
        float v1 = __shfl_sync(0xffffffffu, og1, sl);
        float v2 = __shfl_sync(0xffffffffu, og2, sl);
        float v3 = __shfl_sync(0xffffffffu, og3, sl);
        int c = sl * 4;
        float2 w0 = *(const float2*)&Wps[(c + 0) * 64 + d0];
        float2 w1 = *(const float2*)&Wps[(c + 1) * 64 + d0];
        float2 w2 = *(const float2*)&Wps[(c + 2) * 64 + d0];
        float2 w3 = *(const float2*)&Wps[(c + 3) * 64 + d0];
        y0 += v0 * w0.x + v1 * w1.x + v2 * w2.x + v3 * w3.x;
        y1 += v0 * w0.y + v1 * w1.y + v2 * w2.y + v3 * w3.y;
    }
    int b = g >> 4;
    int t = g & 15;
    float2* out = (float2*)&g_y[(((size_t)(b * N_ + dst)) * T_ + t) * D_];
    out[lane] = make_float2(y0, y1);
}

// ---------------- K,V GEMM: g_kv[rn][0:128] = g_y[rn] @ Wqkv[:,64:192] -------
__global__ void __launch_bounds__(256) k_qkv(const float* __restrict__ Wqkv,
                                             const float* __restrict__ bqkv) {
    __shared__ float Ys[64 * 64];     // [r][k]
    __shared__ float Ws[64 * 128];    // [k][c]
    int tid = threadIdx.x;
    int rb = blockIdx.x * 64;
    for (int i = tid; i < 4096; i += 256) {
        int rr = i >> 6, k = i & 63;
        Ys[i] = g_y[((size_t)(rb + rr)) * 64 + k];
        (void)rr;
    }
    for (int i = tid; i < 8192; i += 256) {
        int k = i >> 7, c = i & 127;
        Ws[i] = Wqkv[k * 192 + 64 + c];
    }
    __syncthreads();
    int tx = tid & 15, ty = tid >> 4;
    int c0 = tx * 8, r0 = ty * 4;
    float acc[4][8];
#pragma unroll
    for (int i = 0; i < 4; i++)
#pragma unroll
        for (int j = 0; j < 8; j++) acc[i][j] = 0.f;
#pragma unroll 8
    for (int k = 0; k < 64; k++) {
        float a0 = Ys[(r0 + 0) * 64 + k];
        float a1 = Ys[(r0 + 1) * 64 + k];
        float a2 = Ys[(r0 + 2) * 64 + k];
        float a3 = Ys[(r0 + 3) * 64 + k];
        float4 b0 = *(const float4*)&Ws[k * 128 + c0];
        float4 b1 = *(const float4*)&Ws[k * 128 + c0 + 4];
        acc[0][0] += a0 * b0.x; acc[0][1] += a0 * b0.y; acc[0][2] += a0 * b0.z; acc[0][3] += a0 * b0.w;
        acc[0][4] += a0 * b1.x; acc[0][5] += a0 * b1.y; acc[0][6] += a0 * b1.z; acc[0][7] += a0 * b1.w;
        acc[1][0] += a1 * b0.x; acc[1][1] += a1 * b0.y; acc[1][2] += a1 * b0.z; acc[1][3] += a1 * b0.w;
        acc[1][4] += a1 * b1.x; acc[1][5] += a1 * b1.y; acc[1][6] += a1 * b1.z; acc[1][7] += a1 * b1.w;
        acc[2][0] += a2 * b0.x; acc[2][1] += a2 * b0.y; acc[2][2] += a2 * b0.z; acc[2][3] += a2 * b0.w;
        acc[2][4] += a2 * b1.x; acc[2][5] += a2 * b1.y; acc[2][6] += a2 * b1.z; acc[2][7] += a2 * b1.w;
        acc[3][0] += a3 * b0.x; acc[3][1] += a3 * b0.y; acc[3][2] += a3 * b0.z; acc[3][3] += a3 * b0.w;
        acc[3][4] += a3 * b1.x; acc[3][5] += a3 * b1.y; acc[3][6] += a3 * b1.z; acc[3][7] += a3 * b1.w;
    }
    float4 bb0 = *(const float4*)&bqkv[64 + c0];
    float4 bb1 = *(const float4*)&bqkv[64 + c0 + 4];
#pragma unroll
    for (int i = 0; i < 4; i++) {
        size_t rn = rb + r0 + i;
        float4 o0 = make_float4(acc[i][0] + bb0.x, acc[i][1] + bb0.y, acc[i][2] + bb0.z, acc[i][3] + bb0.w);
        float4 o1 = make_float4(acc[i][4] + bb1.x, acc[i][5] + bb1.y, acc[i][6] + bb1.z, acc[i][7] + bb1.w);
        *(float4*)&g_kv[rn * 128 + c0] = o0;
        *(float4*)&g_kv[rn * 128 + c0 + 4] = o1;
    }
}

// ---------------- Q GEMM (t=15 rows only): g_q = y15 @ Wqkv[:,0:64] ----------
__global__ void __launch_bounds__(256) k_q(const float* __restrict__ Wqkv,
                                           const float* __restrict__ bqkv) {
    __shared__ float Ys[64 * 64];
    __shared__ float Ws[64 * 64];
    int tid = threadIdx.x;
    int rb = blockIdx.x * 64;
    for (int i = tid; i < 4096; i += 256) {
        int rr = i >> 6, k = i & 63;
        int gr = rb + rr;
        Ys[i] = (gr < BN_) ? g_y[(((size_t)gr) * 16 + 15) * 64 + k] : 0.f;
    }
    for (int i = tid; i < 4096; i += 256) {
        int k = i >> 6, c = i & 63;
        Ws[i] = Wqkv[k * 192 + c];
    }
    __syncthreads();
    int tx = tid & 15, ty = tid >> 4;
    int c0 = tx * 4, r0 = ty * 4;
    float acc[4][4];
#pragma unroll
    for (int i = 0; i < 4; i++)
#pragma unroll
        for (int j = 0; j < 4; j++) acc[i][j] = 0.f;
#pragma unroll 16
    for (int k = 0; k < 64; k++) {
        float a0 = Ys[(r0 + 0) * 64 + k];
        float a1 = Ys[(r0 + 1) * 64 + k];
        float a2 = Ys[(r0 + 2) * 64 + k];
        float a3 = Ys[(r0 + 3) * 64 + k];
        float4 bv = *(const float4*)&Ws[k * 64 + c0];
        acc[0][0] += a0 * bv.x; acc[0][1] += a0 * bv.y; acc[0][2] += a0 * bv.z; acc[0][3] += a0 * bv.w;
        acc[1][0] += a1 * bv.x; acc[1][1] += a1 * bv.y; acc[1][2] += a1 * bv.z; acc[1][3] += a1 * bv.w;
        acc[2][0] += a2 * bv.x; acc[2][1] += a2 * bv.y; acc[2][2] += a2 * bv.z; acc[2][3] += a2 * bv.w;
        acc[3][0] += a3 * bv.x; acc[3][1] += a3 * bv.y; acc[3][2] += a3 * bv.z; acc[3][3] += a3 * bv.w;
    }
    float4 bb = *(const float4*)&bqkv[c0];
#pragma unroll
    for (int i = 0; i < 4; i++) {
        int gr = rb + r0 + i;
        if (gr < BN_) {
            float4 o = make_float4(acc[i][0] + bb.x, acc[i][1] + bb.y, acc[i][2] + bb.z, acc[i][3] + bb.w);
            *(float4*)&g_q[(size_t)gr * 64 + c0] = o;
        }
    }
}

// ---------------- attention (per row) + Wo + residual + LN1 ------------------
__global__ void __launch_bounds__(256) k_attn2(const float* __restrict__ Wo,
                                               const float* __restrict__ bo,
                                               const float* __restrict__ ln1g,
                                               const float* __restrict__ ln1b) {
    __shared__ float Wos[64 * 64];
    __shared__ float bos[64], g1s[64], b1s[64];
    __shared__ float sq[8][64];
    int tid = threadIdx.x;
    for (int i = tid; i < 4096; i += 256) Wos[i] = Wo[i];
    if (tid < 64) { bos[tid] = bo[tid]; g1s[tid] = ln1g[tid]; b1s[tid] = ln1b[tid]; }
    __syncthreads();
    int wid = tid >> 5, lane = tid & 31;
    int r = blockIdx.x * 8 + wid;
    int dcol = lane * 2;
    float2 qv = *(const float2*)&g_q[(size_t)r * 64 + dcol];
    sq[wid][dcol] = qv.x; sq[wid][dcol + 1] = qv.y;
    __syncwarp();
    int t = lane & 15, grp = lane >> 4;
    const float* kbase = &g_kv[((size_t)(r * 16 + t)) * 128 + grp * 32];
    const float* qq = &sq[wid][grp * 32];
    float s0 = 0.f, s1 = 0.f;
#pragma unroll
    for (int j = 0; j < 16; j++) { s0 += qq[j] * kbase[j]; s1 += qq[16 + j] * kbase[16 + j]; }
    s0 *= 0.25f; s1 *= 0.25f;
    float m0 = s0, m1 = s1;
#pragma unroll
    for (int off = 1; off < 16; off <<= 1) {
        m0 = fmaxf(m0, __shfl_xor_sync(0xffffffffu, m0, off));
        m1 = fmaxf(m1, __shfl_xor_sync(0xffffffffu, m1, off));
    }
    float p0 = __expf(s0 - m0), p1 = __expf(s1 - m1);
    float dn0 = p0, dn1 = p1;
#pragma unroll
    for (int off = 1; off < 16; off <<= 1) {
        dn0 += __shfl_xor_sync(0xffffffffu, dn0, off);
        dn1 += __shfl_xor_sync(0xffffffffu, dn1, off);
    }
    p0 /= dn0; p1 /= dn1;
    // ctx: lane owns output dims dcol, dcol+1 (head hd = lane>>3)
    int hd = lane >> 3;
    int srcbase = (hd >> 1) * 16;
    int sel = hd & 1;
    float c0 = 0.f, c1 = 0.f;
#pragma unroll
    for (int tt = 0; tt < 16; tt++) {
        float pa = __shfl_sync(0xffffffffu, p0, srcbase + tt);
        float pb = __shfl_sync(0xffffffffu, p1, srcbase + tt);
        float pv = sel ? pb : pa;
        float2 v2 = *(const float2*)&g_kv[((size_t)(r * 16 + tt)) * 128 + 64 + dcol];
        c0 += pv * v2.x; c1 += pv * v2.y;
    }
    // out = ctx @ Wo + bo
    float o0 = bos[dcol], o1 = bos[dcol + 1];
#pragma unroll
    for (int jj = 0; jj < 32; jj++) {
        float ca = __shfl_sync(0xffffffffu, c0, jj);
        float cb = __shfl_sync(0xffffffffu, c1, jj);
        float2 wA = *(const float2*)&Wos[(2 * jj) * 64 + dcol];
        float2 wB = *(const float2*)&Wos[(2 * jj + 1) * 64 + dcol];
        o0 += ca * wA.x + cb * wB.x;
        o1 += ca * wA.y + cb * wB.y;
    }
    float2 yv = *(const float2*)&g_y[((size_t)(r * 16 + 15)) * 64 + dcol];
    float r0v = yv.x + o0, r1v = yv.y + o1;
    float su = r0v + r1v, s2 = r0v * r0v + r1v * r1v;
#pragma unroll
    for (int off = 1; off < 32; off <<= 1) {
        su += __shfl_xor_sync(0xffffffffu, su, off);
        s2 += __shfl_xor_sync(0xffffffffu, s2, off);
    }
    float mu = su * (1.f / 64.f);
    float var = s2 * (1.f / 64.f) - mu * mu;
    float inv = rsqrtf(var + 1e-5f);
    float2 z;
    z.x = (r0v - mu) * inv * g1s[dcol] + b1s[dcol];
    z.y = (r1v - mu) * inv * g1s[dcol + 1] + b1s[dcol + 1];
    *(float2*)&g_z[(size_t)r * 64 + dcol] = z;
}

// ---------------- FFN layer 1: relu(Z @ W1 + b1) -----------------------------
__global__ void __launch_bounds__(256) k_ffn1(const float* __restrict__ W1,
                                              const float* __restrict__ b1) {
    __shared__ float Zs[64 * 64];    // [r][k]
    __shared__ float W1s[64 * 64];   // [k][c]
    int tid = threadIdx.x;
    int rb = blockIdx.x * 64;
    int cb = blockIdx.y * 64;
    for (int i = tid; i < 4096; i += 256) {
        int rr = i >> 6, k = i & 63;
        int gr = rb + rr;
        Zs[i] = (gr < BN_) ? g_z[(size_t)gr * 64 + k] : 0.f;
    }
    for (int i = tid; i < 4096; i += 256) {
        int k = i >> 6, c = i & 63;
        W1s[i] = W1[(size_t)k * FF_ + cb + c];
    }
    __syncthreads();
    int tx = tid & 15, ty = tid >> 4;
    int r0 = ty * 4, c0 = tx * 4;
    float acc[4][4];
#pragma unroll
    for (int i = 0; i < 4; i++)
#pragma unroll
        for (int j = 0; j < 4; j++) acc[i][j] = 0.f;
#pragma unroll 16
    for (int kk = 0; kk < 64; kk++) {
        float a0 = Zs[(r0 + 0) * 64 + kk];
        float a1 = Zs[(r0 + 1) * 64 + kk];
        float a2 = Zs[(r0 + 2) * 64 + kk];
        float a3 = Zs[(r0 + 3) * 64 + kk];
        float4 bv = *(const float4*)&W1s[kk * 64 + c0];
        acc[0][0] += a0 * bv.x; acc[0][1] += a0 * bv.y; acc[0][2] += a0 * bv.z; acc[0][3] += a0 * bv.w;
        acc[1][0] += a1 * bv.x; acc[1][1] += a1 * bv.y; acc[1][2] += a1 * bv.z; acc[1][3] += a1 * bv.w;
        acc[2][0] += a2 * bv.x; acc[2][1] += a2 * bv.y; acc[2][2] += a2 * bv.z; acc[2][3] += a2 * bv.w;
        acc[3][0] += a3 * bv.x; acc[3][1] += a3 * bv.y; acc[3][2] += a3 * bv.z; acc[3][3] += a3 * bv.w;
    }
    int col = cb + c0;
    float4 bb = *(const float4*)&b1[col];
#pragma unroll
    for (int i = 0; i < 4; i++) {
        int gr = rb + r0 + i;
        if (gr < BN_) {
            float4 o;
            o.x = fmaxf(acc[i][0] + bb.x, 0.f);
            o.y = fmaxf(acc[i][1] + bb.y, 0.f);
            o.z = fmaxf(acc[i][2] + bb.z, 0.f);
            o.w = fmaxf(acc[i][3] + bb.w, 0.f);
            *(float4*)&g_ff[(size_t)gr * FF_ + col] = o;
        }
    }
}

// ---------------- FFN layer 2, split-K into 4 planes -------------------------
__global__ void __launch_bounds__(256) k_ffn2s(const float* __restrict__ W2) {
    __shared__ float Fs[32 * 64];    // [r][k]
    __shared__ float W2s[64 * 64];   // [k][d]
    int tid = threadIdx.x;
    int rb = blockIdx.x * 32;
    int kc0 = blockIdx.y * 512;
    int tx = tid & 15, ty = tid >> 4;
    int r0 = ty * 2, c0 = tx * 4;
    float acc[2][4];
#pragma unroll
    for (int i = 0; i < 2; i++)
#pragma unroll
        for (int j = 0; j < 4; j++) acc[i][j] = 0.f;
    for (int kc = kc0; kc < kc0 + 512; kc += 64) {
        for (int i = tid; i < 2048; i += 256) {
            int rr = i >> 6, k = i & 63;
            Fs[i] = g_ff[(size_t)(rb + rr) * FF_ + kc + k];
        }
        for (int i = tid; i < 4096; i += 256) {
            int k = i >> 6, d = i & 63;
            W2s[i] = W2[(size_t)(kc + k) * 64 + d];
        }
        __syncthreads();
#pragma unroll 16
        for (int kk = 0; kk < 64; kk++) {
            float a0 = Fs[(r0 + 0) * 64 + kk];
            float a1 = Fs[(r0 + 1) * 64 + kk];
            float4 bv = *(const float4*)&W2s[kk * 64 + c0];
            acc[0][0] += a0 * bv.x; acc[0][1] += a0 * bv.y; acc[0][2] += a0 * bv.z; acc[0][3] += a0 * bv.w;
            acc[1][0] += a1 * bv.x; acc[1][1] += a1 * bv.y; acc[1][2] += a1 * bv.z; acc[1][3] += a1 * bv.w;
        }
        __syncthreads();
    }
    float* plane = g_acc[blockIdx.y];
#pragma unroll
    for (int i = 0; i < 2; i++) {
        int gr = rb + r0 + i;
        *(float4*)&plane[(size_t)gr * 64 + c0] =
            make_float4(acc[i][0], acc[i][1], acc[i][2], acc[i][3]);
    }
}

// ---------------- sum planes + b2 + residual + LN2 -> out --------------------
__global__ void __launch_bounds__(256) k_ln2(const float* __restrict__ b2,
                                             const float* __restrict__ ln2g,
                                             const float* __restrict__ ln2b,
                                             float* __restrict__ out) {
    int tid = threadIdx.x, wid = tid >> 5, lane = tid & 31;
    int r = blockIdx.x * 8 + wid;
    int d = lane * 2;
    float2 zr = *(const float2*)&g_z[(size_t)r * 64 + d];
    float2 bb = *(const float2*)&b2[d];
    float v0 = zr.x + bb.x, v1 = zr.y + bb.y;
#pragma unroll
    for (int s = 0; s < 4; s++) {
        float2 a = *(const float2*)&g_acc[s][(size_t)r * 64 + d];
        v0 += a.x; v1 += a.y;
    }
    float su = v0 + v1, s2 = v0 * v0 + v1 * v1;
#pragma unroll
    for (int off = 1; off < 32; off <<= 1) {
        su += __shfl_xor_sync(0xffffffffu, su, off);
        s2 += __shfl_xor_sync(0xffffffffu, s2, off);
    }
    float mu = su * (1.f / 64.f);
    float var = s2 * (1.f / 64.f) - mu * mu;
    float inv = rsqrtf(var + 1e-5f);
    float2 gg = *(const float2*)&ln2g[d];
    float2 be = *(const float2*)&ln2b[d];
    float2 o;
    o.x = (v0 - mu) * inv * gg.x + be.x;
    o.y = (v1 - mu) * inv * gg.y + be.y;
    *(float2*)&out[(size_t)r * 64 + d] = o;
}

// ---------------- launch ----------------------------------------------------
extern "C" void kernel_launch(void* const* d_in, const int* in_sizes, int n_in,
                              void* d_out, int out_size) {
    const float* x_seq    = (const float*)d_in[0];
    const int*   eidx     = (const int*)d_in[1];
    const float* eweight  = (const float*)d_in[2];
    const float* W_gat    = (const float*)d_in[3];
    const float* att_src  = (const float*)d_in[4];
    const float* att_dst  = (const float*)d_in[5];
    const float* W_edge   = (const float*)d_in[6];
    const float* att_edge = (const float*)d_in[7];
    const float* gat_bias = (const float*)d_in[8];
    const float* W_proj   = (const float*)d_in[9];
    const float* b_proj   = (const float*)d_in[10];
    const float* Wqkv     = (const float*)d_in[11];
    const float* bqkv     = (const float*)d_in[12];
    const float* Wo       = (const float*)d_in[13];
    const float* bo       = (const float*)d_in[14];
    const float* ln1_g    = (const float*)d_in[15];
    const float* ln1_b    = (const float*)d_in[16];
    const float* W1       = (const float*)d_in[17];
    const float* b1       = (const float*)d_in[18];
    const float* W2       = (const float*)d_in[19];
    const float* b2       = (const float*)d_in[20];
    const float* ln2_g    = (const float*)d_in[21];
    const float* ln2_b    = (const float*)d_in[22];
    float* out = (float*)d_out;

    k_prep<<<1, 256>>>(eweight, W_edge, att_edge);
    k_count<<<(ET_ + 255) / 256, 256>>>(eidx);
    k_scan<<<1, 1024>>>();
    k_scatter<<<(ET_ + 255) / 256, 256>>>(eidx);
    k_h<<<GN_ / 8, 256>>>(x_seq, W_gat, att_src, att_dst);
    k_agg<<<GN_ / 8, 256>>>(eidx, eweight, gat_bias, W_proj, b_proj);
    k_qkv<<<GN_ / 64, 256>>>(Wqkv, bqkv);
    k_q<<<(BN_ + 63) / 64, 256>>>(Wqkv, bqkv);
    k_attn2<<<BN_ / 8, 256>>>(Wo, bo, ln1_g, ln1_b);
    {
        dim3 grid((BN_ + 63) / 64, FF_ / 64);
        k_ffn1<<<grid, 256>>>(W1, b1);
    }
    {
        dim3 grid(BN_ / 32, 4);
        k_ffn2s<<<grid, 256>>>(W2);
    }
    k_ln2<<<BN_ / 8, 256>>>(b2, ln2_g, ln2_b, out);
}